// round 13
// baseline (speedup 1.0000x reference)
#include <cuda_runtime.h>

// ---------------- problem constants ----------------
// B=2, C=21, H=W=512, pooled 128x128, K=11 (radius 5), 5 steps, pad=(0,0)

// ---------------- scratch (device globals; no mallocs allowed) ----------------
__device__ float g_unary[11010048];   // [2][21][512][512]
__device__ float g_qb[688128];        // [2][21][128][128]
__device__ float g_msgp[1376256];     // [2 tap-groups][2][21][128][128] partial messages
__device__ float g_kcomb[3964928];    // [2][128y][121j][128x]  (y-major, j inner-contiguous rows)
__device__ float g_rgbp[98304];       // [2][3][128][128]    (already /13)

// ---------------- 4x4 avg-pool of x, folded /13 ----------------
__global__ void k_poolrgb(const float* __restrict__ x) {
  int idx = blockIdx.x * 256 + threadIdx.x;  // over 2*3*128*128
  if (idx >= 98304) return;
  int xp = idx & 127, yp = (idx >> 7) & 127, c = idx >> 14;  // c = b*3+ch
  const float* p = x + ((size_t)c << 18) + ((yp * 4) << 9) + (xp * 4);
  float s = 0.f;
#pragma unroll
  for (int i = 0; i < 4; i++)
#pragma unroll
    for (int j = 0; j < 4; j++) s += p[(i << 9) + j];
  g_rgbp[idx] = s * (1.0f / 208.0f);  // /16 pool, /13 feature scale
}

// ---------------- combined pairwise kernel: w1*bilateral + w2*spatial ----------------
// writes g_kcomb[b][y][j][x]
__global__ void k_kernels(const float* __restrict__ pw) {
  __shared__ float rs[3][18][42];
  __shared__ float sA[121], sS[121];
  const int b  = blockIdx.z;
  const int x0 = blockIdx.x * 32, y0 = blockIdx.y * 8;
  const int tx = threadIdx.x, ty = threadIdx.y;
  const int tid = ty * 32 + tx;
  if (tid < 121) {
    int dy = tid / 11 - 5, dx = tid % 11 - 5;
    float d2 = (float)(dy * dy + dx * dx);
    sA[tid] = __expf(-d2 * (1.0f / 800.0f));  // pooled YX/80: (4d/80)^2/2
    sS[tid] = __expf(-d2 * (8.0f / 9.0f));    // pooled YX/3 : (4d/3)^2/2
  }
  for (int i = tid; i < 3 * 18 * 42; i += 256) {
    int c = i / 756, rem = i % 756, yy = rem / 42, xx = rem % 42;
    int gy = y0 + yy - 5, gx = x0 + xx - 5;
    float v = 0.f;
    if (gy >= 0 && gy < 128 && gx >= 0 && gx < 128)
      v = g_rgbp[((b * 3 + c) << 14) + (gy << 7) + gx];
    rs[c][yy][xx] = v;
  }
  __syncthreads();
  const float w1 = pw[0], w2 = pw[1];
  const float r0 = rs[0][ty + 5][tx + 5];
  const float r1 = rs[1][ty + 5][tx + 5];
  const float r2 = rs[2][ty + 5][tx + 5];
  const int y = y0 + ty, xg = x0 + tx;
  float* outp = g_kcomb + (((size_t)(b * 128 + y) * 121) << 7) + xg;
  for (int dy = 0; dy < 11; dy++) {
    for (int dx = 0; dx < 11; dx++) {
      int j = dy * 11 + dx;
      int ny = y + dy - 5, nx = xg + dx - 5;
      float val = 0.f;  // OOB entries multiply zero-padded Q patches -> store 0
      if (ny >= 0 && ny < 128 && nx >= 0 && nx < 128) {
        float a = rs[0][ty + dy][tx + dx] - r0;
        float bb = rs[1][ty + dy][tx + dx] - r1;
        float cc = rs[2][ty + dy][tx + dx] - r2;
        float d2 = a * a + bb * bb + cc * cc;
        val = fmaf(w1 * sA[j], __expf(-0.5f * d2), w2 * sS[j]);
      }
      outp[j << 7] = val;
    }
  }
}

// ---------------- fused: conv(3->21) -> write unary -> softmax -> 4x4 pool ----------------
// block 32x8, grid (16,64,2)
__global__ void k_convsoft(const float* __restrict__ x, const float* __restrict__ w,
                           const float* __restrict__ bias, const float* __restrict__ uwp) {
  __shared__ float xs[3][10][34];
  __shared__ float ws[567];
  __shared__ float bs[21];
  __shared__ float ps[8][8][21];
  const int b  = blockIdx.z;
  const int x0 = blockIdx.x * 32, y0 = blockIdx.y * 8;
  const int tx = threadIdx.x, ty = threadIdx.y;
  const int tid = ty * 32 + tx;
  const float uw = uwp[0];
  for (int i = tid; i < 567; i += 256) ws[i] = w[i];
  if (tid < 21) bs[tid] = bias[tid];
  for (int i = tid; i < 3 * 10 * 34; i += 256) {
    int c = i / 340, rem = i % 340, yy = rem / 34, xx = rem % 34;
    int gy = y0 + yy - 1, gx = x0 + xx - 1;
    float v = 0.f;
    if (gy >= 0 && gy < 512 && gx >= 0 && gx < 512)
      v = x[((size_t)(b * 3 + c) << 18) + (gy << 9) + gx];
    xs[c][yy][xx] = v;
  }
  __syncthreads();
  float r[27];
#pragma unroll
  for (int c = 0; c < 3; c++)
#pragma unroll
    for (int ky = 0; ky < 3; ky++)
#pragma unroll
      for (int kx = 0; kx < 3; kx++)
        r[c * 9 + ky * 3 + kx] = xs[c][ty + ky][tx + kx];
  float* outp = g_unary + ((size_t)b * 21 << 18) + ((y0 + ty) << 9) + (x0 + tx);
  float logit[21];
  float mx = -1e30f;
#pragma unroll
  for (int o = 0; o < 21; o++) {
    float acc = bs[o];
#pragma unroll
    for (int i = 0; i < 27; i++) acc = fmaf(r[i], ws[o * 27 + i], acc);
    outp[(size_t)o << 18] = acc;
    float v = uw * acc;
    logit[o] = v;
    mx = fmaxf(mx, v);
  }
  float s = 0.f;
#pragma unroll
  for (int c = 0; c < 21; c++) { float e = __expf(logit[c] - mx); logit[c] = e; s += e; }
  float inv = __frcp_rn(s);
#pragma unroll
  for (int c = 0; c < 21; c++) {
    float q = logit[c] * inv;
    q += __shfl_down_sync(0xffffffffu, q, 1);
    q += __shfl_down_sync(0xffffffffu, q, 2);
    logit[c] = q;
  }
  if ((tx & 3) == 0) {
#pragma unroll
    for (int c = 0; c < 21; c++) ps[ty][tx >> 2][c] = logit[c];
  }
  __syncthreads();
  for (int i = tid; i < 336; i += 256) {
    int c = i % 21, pxx = (i / 21) & 7, pyy = i / 168;
    float sum = ps[pyy * 4 + 0][pxx][c] + ps[pyy * 4 + 1][pxx][c] +
                ps[pyy * 4 + 2][pxx][c] + ps[pyy * 4 + 3][pxx][c];
    int yp = (y0 >> 2) + pyy, xp = (x0 >> 2) + pxx;
    g_qb[((b * 21 + c) << 14) + (yp << 7) + xp] = sum * 0.0625f;
  }
}

// ---------------- fused: (uw*unary + upsample(msg)) -> softmax -> 4x4 pool ----------------
__global__ void k_softpool(const float* __restrict__ uwp) {
  __shared__ float ms[21][4][10];
  __shared__ float ps[8][8][21];
  const int b  = blockIdx.z;
  const int x0 = blockIdx.x * 32, y0 = blockIdx.y * 8;
  const int tx = threadIdx.x, ty = threadIdx.y;
  const int tid = ty * 32 + tx;
  const float uw = uwp[0];
  {
    int qx0 = (x0 >> 2) - 1, qy0 = (y0 >> 2) - 1;
    for (int i = tid; i < 21 * 4 * 10; i += 256) {
      int c = i / 40, rem = i % 40, yy = rem / 10, xx = rem % 10;
      int gy = min(max(qy0 + yy, 0), 127), gx = min(max(qx0 + xx, 0), 127);
      size_t idx = (size_t)((b * 21 + c) << 14) + (gy << 7) + gx;
      ms[c][yy][xx] = g_msgp[idx] + g_msgp[688128 + idx];
    }
    __syncthreads();
  }
  const int pxp = tx & 3;
  const int ix0 = (tx >> 2) + (pxp >= 2 ? 1 : 0);
  const float wx0 = (pxp == 0) ? 0.375f : (pxp == 1) ? 0.125f : (pxp == 2) ? 0.875f : 0.625f;
  const float wx1 = 1.f - wx0;
  const int pyp = ty & 3;
  const int iy0 = (ty >> 2) + (pyp >= 2 ? 1 : 0);
  const float wy0 = (pyp == 0) ? 0.375f : (pyp == 1) ? 0.125f : (pyp == 2) ? 0.875f : 0.625f;
  const float wy1 = 1.f - wy0;
  const int y = y0 + ty, xg = x0 + tx;
  const float* up = g_unary + ((size_t)b * 21 << 18) + (y << 9) + xg;
  float logit[21];
  float mx = -1e30f;
#pragma unroll
  for (int c = 0; c < 21; c++) {
    float v = uw * up[(size_t)c << 18];
    float a  = wx0 * ms[c][iy0][ix0]     + wx1 * ms[c][iy0][ix0 + 1];
    float bb = wx0 * ms[c][iy0 + 1][ix0] + wx1 * ms[c][iy0 + 1][ix0 + 1];
    v += wy0 * a + wy1 * bb;
    logit[c] = v;
    mx = fmaxf(mx, v);
  }
  float s = 0.f;
#pragma unroll
  for (int c = 0; c < 21; c++) { float e = __expf(logit[c] - mx); logit[c] = e; s += e; }
  float inv = __frcp_rn(s);
#pragma unroll
  for (int c = 0; c < 21; c++) {
    float q = logit[c] * inv;
    q += __shfl_down_sync(0xffffffffu, q, 1);
    q += __shfl_down_sync(0xffffffffu, q, 2);
    logit[c] = q;
  }
  if ((tx & 3) == 0) {
#pragma unroll
    for (int c = 0; c < 21; c++) ps[ty][tx >> 2][c] = logit[c];
  }
  __syncthreads();
  for (int i = tid; i < 336; i += 256) {
    int c = i % 21, pxx = (i / 21) & 7, pyy = i / 168;
    float sum = ps[pyy * 4 + 0][pxx][c] + ps[pyy * 4 + 1][pxx][c] +
                ps[pyy * 4 + 2][pxx][c] + ps[pyy * 4 + 3][pxx][c];
    int yp = (y0 >> 2) + pyy, xp = (x0 >> 2) + pxx;
    g_qb[((b * 21 + c) << 14) + (yp << 7) + xp] = sum * 0.0625f;
  }
}

// ---------------- pixel-adaptive 11x11 message at 128x128 ----------------
// Tap-split x2 (g0: k rows 0..5, g1: 6..10), channel-split x2 (11 ch).
// Block (16,4)=64 thr covers 64px x 4 rows; per thread 4px x 11ch.
// smem qs[11][9][80] = 31.7KB -> 5 blocks/SM, no spills at (64,5) reg cap.
// kv software-pipelined: first half prefetched before __syncthreads, each
// next half-batch issued while current half's FMAs run.
// grid (2,32,8): z = b*4 + g*2 + cg.
__global__ __launch_bounds__(64, 5) void k_pac() {
  __shared__ float qs[11][9][80];
  const int bz = blockIdx.z;
  const int b  = bz >> 2;
  const int g  = (bz >> 1) & 1;
  const int cg = bz & 1;
  const int s  = g * 6;
  const int nrr = 6 - g;              // g0: rr 0..5, g1: rr 6..10
  const int c0 = cg * 11;             // cg=1 covers c 11..20 (10 real + pad)
  const int x0 = blockIdx.x * 64;
  const int y0 = blockIdx.y * 4;
  const int tx = threadIdx.x;         // 0..15
  const int ty = threadIdx.y;         // 0..3
  const int tid = ty * 16 + tx;
  const int qy0 = y0 - 5 + s;
  const int y  = y0 + ty;
  const int xb = tx * 4;

  // prefetch kv half A of first rr BEFORE the fill/sync (independent of smem)
  const float* krow = g_kcomb + (((size_t)(b * 128 + y) * 121) << 7) + x0 + xb;
  float4 kvA[6], kvB[5];
  {
    const float4* kb = reinterpret_cast<const float4*>(krow + ((s * 11) << 7));
#pragma unroll
    for (int d = 0; d < 6; d++) kvA[d] = __ldg(kb + (d << 5));
  }

  // zero-fill smem (flat float4, no index math)
  {
    float4 z4 = make_float4(0.f, 0.f, 0.f, 0.f);
    float4* qsf = reinterpret_cast<float4*>(&qs[0][0][0]);
    for (int i = tid; i < 1980; i += 64) qsf[i] = z4;
  }
  __syncthreads();
  // fill valid region; virtual row width 128 -> shift/mask indexing only
  {
    const int rows = nrr + 3;          // 9 (g0) or 8 (g1)
    const int cmax = cg ? 10 : 11;
    for (int i = tid; i < (rows << 7); i += 64) {
      int r = i >> 7, xx = i & 127;
      int gy = qy0 + r, gx = x0 - 5 + xx;
      if (xx < 74 && gy >= 0 && gy < 128 && gx >= 0 && gx < 128) {
        const float* src = g_qb + ((b * 21 + c0) << 14) + (gy << 7) + gx;
        float* dst = &qs[0][r][xx];
        for (int c = 0; c < cmax; c++) dst[c * 720] = src[(size_t)c << 14];
      }
    }
  }
  __syncthreads();

  float acc[11][4];
#pragma unroll
  for (int c = 0; c < 11; c++)
#pragma unroll
    for (int o = 0; o < 4; o++) acc[c][o] = 0.f;

  for (int rr = s; rr < s + nrr; rr++) {
    const float4* kb = reinterpret_cast<const float4*>(krow + ((rr * 11) << 7));
    // issue kv half B for this rr now (overlaps half-A compute)
#pragma unroll
    for (int d = 0; d < 5; d++) kvB[d] = __ldg(kb + ((d + 6) << 5));
    const int r = ty + rr - s;   // smem row index
    // ---- half A: dx 0..5 (q floats xb..xb+8) ----
#pragma unroll
    for (int c = 0; c < 11; c++) {
      const float4* qp = reinterpret_cast<const float4*>(&qs[c][r][xb]);
      float4 q0 = qp[0], q1 = qp[1], q2 = qp[2];
      float qf[12] = {q0.x, q0.y, q0.z, q0.w, q1.x, q1.y, q1.z, q1.w,
                      q2.x, q2.y, q2.z, q2.w};
#pragma unroll
      for (int dx = 0; dx < 6; dx++) {
        acc[c][0] = fmaf(kvA[dx].x, qf[dx + 0], acc[c][0]);
        acc[c][1] = fmaf(kvA[dx].y, qf[dx + 1], acc[c][1]);
        acc[c][2] = fmaf(kvA[dx].z, qf[dx + 2], acc[c][2]);
        acc[c][3] = fmaf(kvA[dx].w, qf[dx + 3], acc[c][3]);
      }
    }
    // prefetch kv half A of NEXT rr (overlaps half-B compute)
    if (rr + 1 < s + nrr) {
      const float4* kb2 = reinterpret_cast<const float4*>(krow + (((rr + 1) * 11) << 7));
#pragma unroll
      for (int d = 0; d < 6; d++) kvA[d] = __ldg(kb2 + (d << 5));
    }
    // ---- half B: dx 6..10 (q floats xb+6..xb+13) ----
#pragma unroll
    for (int c = 0; c < 11; c++) {
      const float4* qp = reinterpret_cast<const float4*>(&qs[c][r][xb]);
      float4 q1 = qp[1], q2 = qp[2], q3 = qp[3];
      float qf[12] = {q1.x, q1.y, q1.z, q1.w, q2.x, q2.y, q2.z, q2.w,
                      q3.x, q3.y, q3.z, q3.w};  // qf[k] = q float xb+4+k
#pragma unroll
      for (int d = 0; d < 5; d++) {
        acc[c][0] = fmaf(kvB[d].x, qf[d + 2], acc[c][0]);
        acc[c][1] = fmaf(kvB[d].y, qf[d + 3], acc[c][1]);
        acc[c][2] = fmaf(kvB[d].z, qf[d + 4], acc[c][2]);
        acc[c][3] = fmaf(kvB[d].w, qf[d + 5], acc[c][3]);
      }
    }
  }
  float* mp = g_msgp + (size_t)g * 688128 + ((size_t)(b * 21 + c0) << 14) + (y << 7) + x0 + xb;
#pragma unroll
  for (int c = 0; c < 11; c++) {
    if (c0 + c < 21) {
      float4 v = make_float4(acc[c][0], acc[c][1], acc[c][2], acc[c][3]);
      *reinterpret_cast<float4*>(mp + ((size_t)c << 14)) = v;
    }
  }
}

// ---------------- last step: logQ = uw*unary + upsample(msg) -> d_out ----------------
__global__ void k_final(const float* __restrict__ uwp, float* __restrict__ out) {
  __shared__ float ms[21][4][10];
  const int b  = blockIdx.z;
  const int x0 = blockIdx.x * 32, y0 = blockIdx.y * 8;
  const int tx = threadIdx.x, ty = threadIdx.y;
  const int tid = ty * 32 + tx;
  const float uw = uwp[0];
  {
    int qx0 = (x0 >> 2) - 1, qy0 = (y0 >> 2) - 1;
    for (int i = tid; i < 21 * 4 * 10; i += 256) {
      int c = i / 40, rem = i % 40, yy = rem / 10, xx = rem % 10;
      int gy = min(max(qy0 + yy, 0), 127), gx = min(max(qx0 + xx, 0), 127);
      size_t idx = (size_t)((b * 21 + c) << 14) + (gy << 7) + gx;
      ms[c][yy][xx] = g_msgp[idx] + g_msgp[688128 + idx];
    }
    __syncthreads();
  }
  const int pxp = tx & 3;
  const int ix0 = (tx >> 2) + (pxp >= 2 ? 1 : 0);
  const float wx0 = (pxp == 0) ? 0.375f : (pxp == 1) ? 0.125f : (pxp == 2) ? 0.875f : 0.625f;
  const float wx1 = 1.f - wx0;
  const int pyp = ty & 3;
  const int iy0 = (ty >> 2) + (pyp >= 2 ? 1 : 0);
  const float wy0 = (pyp == 0) ? 0.375f : (pyp == 1) ? 0.125f : (pyp == 2) ? 0.875f : 0.625f;
  const float wy1 = 1.f - wy0;
  const int y = y0 + ty, xg = x0 + tx;
  const float* up = g_unary + ((size_t)b * 21 << 18) + (y << 9) + xg;
  float* op = out + ((size_t)b * 21 << 18) + (y << 9) + xg;
#pragma unroll
  for (int c = 0; c < 21; c++) {
    float v = uw * up[(size_t)c << 18];
    float a  = wx0 * ms[c][iy0][ix0]     + wx1 * ms[c][iy0][ix0 + 1];
    float bb = wx0 * ms[c][iy0 + 1][ix0] + wx1 * ms[c][iy0 + 1][ix0 + 1];
    op[(size_t)c << 18] = v + wy0 * a + wy1 * bb;
  }
}

extern "C" void kernel_launch(void* const* d_in, const int* in_sizes, int n_in,
                              void* d_out, int out_size) {
  const float* x    = (const float*)d_in[0];
  const float* w    = (const float*)d_in[1];
  const float* bias = (const float*)d_in[2];
  const float* uw   = (const float*)d_in[3];
  const float* pw   = (const float*)d_in[4];
  float* out = (float*)d_out;
  (void)in_sizes; (void)n_in; (void)out_size;

  dim3 b32x8(32, 8);
  k_poolrgb<<<384, 256>>>(x);
  k_kernels<<<dim3(4, 16, 2), b32x8>>>(pw);
  k_convsoft<<<dim3(16, 64, 2), b32x8>>>(x, w, bias, uw);
  for (int t = 0; t < 5; t++) {
    k_pac<<<dim3(2, 32, 8), dim3(16, 4)>>>();
    if (t < 4) k_softpool<<<dim3(16, 64, 2), b32x8>>>(uw);
    else       k_final<<<dim3(16, 64, 2), b32x8>>>(uw, out);
  }
}

// round 15
// speedup vs baseline: 1.1238x; 1.1238x over previous
#include <cuda_runtime.h>

// ---------------- problem constants ----------------
// B=2, C=21, H=W=512, pooled 128x128, K=11 (radius 5), 5 steps, pad=(0,0)

// ---------------- scratch (device globals; no mallocs allowed) ----------------
__device__ float g_unary[11010048];   // [2][21][512][512]
__device__ float g_qb[688128];        // [2][21][128][128]
__device__ float g_msgp[2752512];     // [4 tap-groups][2][21][128][128] partial messages
__device__ float g_kcomb[3964928];    // [2][128y][121j][128x]  (y-major, j inner-contiguous rows)
__device__ float g_rgbp[98304];       // [2][3][128][128]    (already /13)

// ---------------- 4x4 avg-pool of x, folded /13 ----------------
__global__ void k_poolrgb(const float* __restrict__ x) {
  int idx = blockIdx.x * 256 + threadIdx.x;  // over 2*3*128*128
  if (idx >= 98304) return;
  int xp = idx & 127, yp = (idx >> 7) & 127, c = idx >> 14;  // c = b*3+ch
  const float* p = x + ((size_t)c << 18) + ((yp * 4) << 9) + (xp * 4);
  float s = 0.f;
#pragma unroll
  for (int i = 0; i < 4; i++)
#pragma unroll
    for (int j = 0; j < 4; j++) s += p[(i << 9) + j];
  g_rgbp[idx] = s * (1.0f / 208.0f);  // /16 pool, /13 feature scale
}

// ---------------- combined pairwise kernel: w1*bilateral + w2*spatial ----------------
// writes g_kcomb[b][y][j][x]
__global__ void k_kernels(const float* __restrict__ pw) {
  __shared__ float rs[3][18][42];
  __shared__ float sA[121], sS[121];
  const int b  = blockIdx.z;
  const int x0 = blockIdx.x * 32, y0 = blockIdx.y * 8;
  const int tx = threadIdx.x, ty = threadIdx.y;
  const int tid = ty * 32 + tx;
  if (tid < 121) {
    int dy = tid / 11 - 5, dx = tid % 11 - 5;
    float d2 = (float)(dy * dy + dx * dx);
    sA[tid] = __expf(-d2 * (1.0f / 800.0f));  // pooled YX/80: (4d/80)^2/2
    sS[tid] = __expf(-d2 * (8.0f / 9.0f));    // pooled YX/3 : (4d/3)^2/2
  }
  for (int i = tid; i < 3 * 18 * 42; i += 256) {
    int c = i / 756, rem = i % 756, yy = rem / 42, xx = rem % 42;
    int gy = y0 + yy - 5, gx = x0 + xx - 5;
    float v = 0.f;
    if (gy >= 0 && gy < 128 && gx >= 0 && gx < 128)
      v = g_rgbp[((b * 3 + c) << 14) + (gy << 7) + gx];
    rs[c][yy][xx] = v;
  }
  __syncthreads();
  const float w1 = pw[0], w2 = pw[1];
  const float r0 = rs[0][ty + 5][tx + 5];
  const float r1 = rs[1][ty + 5][tx + 5];
  const float r2 = rs[2][ty + 5][tx + 5];
  const int y = y0 + ty, xg = x0 + tx;
  float* outp = g_kcomb + (((size_t)(b * 128 + y) * 121) << 7) + xg;
  for (int dy = 0; dy < 11; dy++) {
    for (int dx = 0; dx < 11; dx++) {
      int j = dy * 11 + dx;
      int ny = y + dy - 5, nx = xg + dx - 5;
      float val = 0.f;  // OOB entries multiply zero-padded Q patches -> store 0
      if (ny >= 0 && ny < 128 && nx >= 0 && nx < 128) {
        float a = rs[0][ty + dy][tx + dx] - r0;
        float bb = rs[1][ty + dy][tx + dx] - r1;
        float cc = rs[2][ty + dy][tx + dx] - r2;
        float d2 = a * a + bb * bb + cc * cc;
        val = fmaf(w1 * sA[j], __expf(-0.5f * d2), w2 * sS[j]);
      }
      outp[j << 7] = val;
    }
  }
}

// ---------------- fused: conv(3->21) -> write unary -> softmax -> 4x4 pool ----------------
// block 32x8, grid (16,64,2)
__global__ void k_convsoft(const float* __restrict__ x, const float* __restrict__ w,
                           const float* __restrict__ bias, const float* __restrict__ uwp) {
  __shared__ float xs[3][10][34];
  __shared__ float ws[567];
  __shared__ float bs[21];
  __shared__ float ps[8][8][21];
  const int b  = blockIdx.z;
  const int x0 = blockIdx.x * 32, y0 = blockIdx.y * 8;
  const int tx = threadIdx.x, ty = threadIdx.y;
  const int tid = ty * 32 + tx;
  const float uw = uwp[0];
  for (int i = tid; i < 567; i += 256) ws[i] = w[i];
  if (tid < 21) bs[tid] = bias[tid];
  for (int i = tid; i < 3 * 10 * 34; i += 256) {
    int c = i / 340, rem = i % 340, yy = rem / 34, xx = rem % 34;
    int gy = y0 + yy - 1, gx = x0 + xx - 1;
    float v = 0.f;
    if (gy >= 0 && gy < 512 && gx >= 0 && gx < 512)
      v = x[((size_t)(b * 3 + c) << 18) + (gy << 9) + gx];
    xs[c][yy][xx] = v;
  }
  __syncthreads();
  float r[27];
#pragma unroll
  for (int c = 0; c < 3; c++)
#pragma unroll
    for (int ky = 0; ky < 3; ky++)
#pragma unroll
      for (int kx = 0; kx < 3; kx++)
        r[c * 9 + ky * 3 + kx] = xs[c][ty + ky][tx + kx];
  float* outp = g_unary + ((size_t)b * 21 << 18) + ((y0 + ty) << 9) + (x0 + tx);
  float logit[21];
  float mx = -1e30f;
#pragma unroll
  for (int o = 0; o < 21; o++) {
    float acc = bs[o];
#pragma unroll
    for (int i = 0; i < 27; i++) acc = fmaf(r[i], ws[o * 27 + i], acc);
    outp[(size_t)o << 18] = acc;
    float v = uw * acc;
    logit[o] = v;
    mx = fmaxf(mx, v);
  }
  float s = 0.f;
#pragma unroll
  for (int c = 0; c < 21; c++) { float e = __expf(logit[c] - mx); logit[c] = e; s += e; }
  float inv = __frcp_rn(s);
#pragma unroll
  for (int c = 0; c < 21; c++) {
    float q = logit[c] * inv;
    q += __shfl_down_sync(0xffffffffu, q, 1);
    q += __shfl_down_sync(0xffffffffu, q, 2);
    logit[c] = q;
  }
  if ((tx & 3) == 0) {
#pragma unroll
    for (int c = 0; c < 21; c++) ps[ty][tx >> 2][c] = logit[c];
  }
  __syncthreads();
  for (int i = tid; i < 336; i += 256) {
    int c = i % 21, pxx = (i / 21) & 7, pyy = i / 168;
    float sum = ps[pyy * 4 + 0][pxx][c] + ps[pyy * 4 + 1][pxx][c] +
                ps[pyy * 4 + 2][pxx][c] + ps[pyy * 4 + 3][pxx][c];
    int yp = (y0 >> 2) + pyy, xp = (x0 >> 2) + pxx;
    g_qb[((b * 21 + c) << 14) + (yp << 7) + xp] = sum * 0.0625f;
  }
}

// ---------------- fused: (uw*unary + upsample(msg)) -> softmax -> 4x4 pool ----------------
__global__ void k_softpool(const float* __restrict__ uwp) {
  __shared__ float ms[21][4][10];
  __shared__ float ps[8][8][21];
  const int b  = blockIdx.z;
  const int x0 = blockIdx.x * 32, y0 = blockIdx.y * 8;
  const int tx = threadIdx.x, ty = threadIdx.y;
  const int tid = ty * 32 + tx;
  const float uw = uwp[0];
  {
    int qx0 = (x0 >> 2) - 1, qy0 = (y0 >> 2) - 1;
    for (int i = tid; i < 21 * 4 * 10; i += 256) {
      int c = i / 40, rem = i % 40, yy = rem / 10, xx = rem % 10;
      int gy = min(max(qy0 + yy, 0), 127), gx = min(max(qx0 + xx, 0), 127);
      size_t idx = (size_t)((b * 21 + c) << 14) + (gy << 7) + gx;
      ms[c][yy][xx] = g_msgp[idx] + g_msgp[688128 + idx] +
                      g_msgp[2 * 688128 + idx] + g_msgp[3 * 688128 + idx];
    }
    __syncthreads();
  }
  const int pxp = tx & 3;
  const int ix0 = (tx >> 2) + (pxp >= 2 ? 1 : 0);
  const float wx0 = (pxp == 0) ? 0.375f : (pxp == 1) ? 0.125f : (pxp == 2) ? 0.875f : 0.625f;
  const float wx1 = 1.f - wx0;
  const int pyp = ty & 3;
  const int iy0 = (ty >> 2) + (pyp >= 2 ? 1 : 0);
  const float wy0 = (pyp == 0) ? 0.375f : (pyp == 1) ? 0.125f : (pyp == 2) ? 0.875f : 0.625f;
  const float wy1 = 1.f - wy0;
  const int y = y0 + ty, xg = x0 + tx;
  const float* up = g_unary + ((size_t)b * 21 << 18) + (y << 9) + xg;
  float logit[21];
  float mx = -1e30f;
#pragma unroll
  for (int c = 0; c < 21; c++) {
    float v = uw * up[(size_t)c << 18];
    float a  = wx0 * ms[c][iy0][ix0]     + wx1 * ms[c][iy0][ix0 + 1];
    float bb = wx0 * ms[c][iy0 + 1][ix0] + wx1 * ms[c][iy0 + 1][ix0 + 1];
    v += wy0 * a + wy1 * bb;
    logit[c] = v;
    mx = fmaxf(mx, v);
  }
  float s = 0.f;
#pragma unroll
  for (int c = 0; c < 21; c++) { float e = __expf(logit[c] - mx); logit[c] = e; s += e; }
  float inv = __frcp_rn(s);
#pragma unroll
  for (int c = 0; c < 21; c++) {
    float q = logit[c] * inv;
    q += __shfl_down_sync(0xffffffffu, q, 1);
    q += __shfl_down_sync(0xffffffffu, q, 2);
    logit[c] = q;
  }
  if ((tx & 3) == 0) {
#pragma unroll
    for (int c = 0; c < 21; c++) ps[ty][tx >> 2][c] = logit[c];
  }
  __syncthreads();
  for (int i = tid; i < 336; i += 256) {
    int c = i % 21, pxx = (i / 21) & 7, pyy = i / 168;
    float sum = ps[pyy * 4 + 0][pxx][c] + ps[pyy * 4 + 1][pxx][c] +
                ps[pyy * 4 + 2][pxx][c] + ps[pyy * 4 + 3][pxx][c];
    int yp = (y0 >> 2) + pyy, xp = (x0 >> 2) + pxx;
    g_qb[((b * 21 + c) << 14) + (yp << 7) + xp] = sum * 0.0625f;
  }
}

// ---------------- pixel-adaptive 11x11 message at 128x128 ----------------
// R8 structure (best known: tap-split x4, channel-split x2, 64px blocks,
// 11 ch x 4 px per thread, kv half-split) with the R12-validated vectorized
// fill: smem origin x0-8 so all chunks are aligned float4, pow2 indexing.
// grid (2,32,16): z = b*8 + g*2 + cg; tap rows [3g,3g+3) (g=3: [9,11)).
__global__ __launch_bounds__(64, 8) void k_pac() {
  __shared__ float qs[11][6][80];     // origin gx = x0-8, gy = qy0
  const int bz = blockIdx.z;
  const int b  = bz >> 3;
  const int g  = (bz >> 1) & 3;
  const int cg = bz & 1;
  const int s  = g * 3;
  const int nrr = (g == 3) ? 2 : 3;
  const int c0 = cg * 11;             // cg=1 covers c 11..20 (10 real + pad)
  const int x0 = blockIdx.x * 64;
  const int y0 = blockIdx.y * 4;
  const int tx = threadIdx.x;         // 0..15
  const int ty = threadIdx.y;         // 0..3
  const int tid = ty * 16 + tx;
  const int qy0 = y0 - 5 + s;
  // zero-fill smem (flat float4, no index math)
  {
    float4 z4 = make_float4(0.f, 0.f, 0.f, 0.f);
    float4* qsf = reinterpret_cast<float4*>(&qs[0][0][0]);
    for (int i = tid; i < 1320; i += 64) qsf[i] = z4;
  }
  __syncthreads();
  // vectorized fill: 6 rows x 20 aligned float4 chunks (virtual 32/row).
  // chunk k covers gx = x0-8+4k -> smem col 4k. All-or-nothing bounds
  // (gx multiple of 4, so chunk is fully in [0,128) or fully out).
  {
    const int cmax = cg ? 10 : 11;
    for (int i = tid; i < 192; i += 64) {
      int r = i >> 5, k = i & 31;
      int gy = qy0 + r, gx = x0 - 8 + (k << 2);
      if (k < 20 && gy >= 0 && gy < 128 && gx >= 0 && gx < 128) {
        const float* src = g_qb + ((b * 21 + c0) << 14) + (gy << 7) + gx;
        float* dst = &qs[0][r][k << 2];
        for (int c = 0; c < cmax; c++)
          *reinterpret_cast<float4*>(dst + c * 480) =
              *reinterpret_cast<const float4*>(src + ((size_t)c << 14));
      }
    }
  }
  __syncthreads();
  const int y  = y0 + ty;
  const int xb = tx * 4;
  float acc[11][4];
#pragma unroll
  for (int c = 0; c < 11; c++)
#pragma unroll
    for (int o = 0; o < 4; o++) acc[c][o] = 0.f;
  for (int rr = s; rr < s + nrr; rr++) {
    const float4* kb = reinterpret_cast<const float4*>(
        g_kcomb + (((size_t)(b * 128 + y) * 121 + rr * 11) << 7) + x0 + xb);
    const int r = ty + rr - s;   // smem row index
    // ---- half A: dx 0..5; q rel floats [3..12] -> slots tx..tx+3 ----
    {
      float4 kv[6];
#pragma unroll
      for (int dx = 0; dx < 6; dx++) kv[dx] = __ldg(kb + (dx << 5));
#pragma unroll
      for (int c = 0; c < 11; c++) {
        const float4* qp = reinterpret_cast<const float4*>(&qs[c][r][0]) + tx;
        float4 q0 = qp[0], q1 = qp[1], q2 = qp[2], q3 = qp[3];
        float qf[16] = {q0.x, q0.y, q0.z, q0.w, q1.x, q1.y, q1.z, q1.w,
                        q2.x, q2.y, q2.z, q2.w, q3.x, q3.y, q3.z, q3.w};
#pragma unroll
        for (int dx = 0; dx < 6; dx++) {
          acc[c][0] = fmaf(kv[dx].x, qf[dx + 3], acc[c][0]);
          acc[c][1] = fmaf(kv[dx].y, qf[dx + 4], acc[c][1]);
          acc[c][2] = fmaf(kv[dx].z, qf[dx + 5], acc[c][2]);
          acc[c][3] = fmaf(kv[dx].w, qf[dx + 6], acc[c][3]);
        }
      }
    }
    // ---- half B: dx 6..10; q rel floats [9..16] -> slots tx+2..tx+4 ----
    {
      float4 kv[5];
#pragma unroll
      for (int d = 0; d < 5; d++) kv[d] = __ldg(kb + ((d + 6) << 5));
#pragma unroll
      for (int c = 0; c < 11; c++) {
        const float4* qp = reinterpret_cast<const float4*>(&qs[c][r][0]) + tx;
        float4 q2 = qp[2], q3 = qp[3], q4 = qp[4];
        float qf[12] = {q2.x, q2.y, q2.z, q2.w, q3.x, q3.y, q3.z, q3.w,
                        q4.x, q4.y, q4.z, q4.w};  // qf[i] = rel float 8+i
#pragma unroll
        for (int d = 0; d < 5; d++) {
          acc[c][0] = fmaf(kv[d].x, qf[d + 1], acc[c][0]);
          acc[c][1] = fmaf(kv[d].y, qf[d + 2], acc[c][1]);
          acc[c][2] = fmaf(kv[d].z, qf[d + 3], acc[c][2]);
          acc[c][3] = fmaf(kv[d].w, qf[d + 4], acc[c][3]);
        }
      }
    }
  }
  float* mp = g_msgp + (size_t)g * 688128 + ((size_t)(b * 21 + c0) << 14) + (y << 7) + x0 + xb;
#pragma unroll
  for (int c = 0; c < 11; c++) {
    if (c0 + c < 21) {
      float4 v = make_float4(acc[c][0], acc[c][1], acc[c][2], acc[c][3]);
      *reinterpret_cast<float4*>(mp + ((size_t)c << 14)) = v;
    }
  }
}

// ---------------- last step: logQ = uw*unary + upsample(msg) -> d_out ----------------
__global__ void k_final(const float* __restrict__ uwp, float* __restrict__ out) {
  __shared__ float ms[21][4][10];
  const int b  = blockIdx.z;
  const int x0 = blockIdx.x * 32, y0 = blockIdx.y * 8;
  const int tx = threadIdx.x, ty = threadIdx.y;
  const int tid = ty * 32 + tx;
  const float uw = uwp[0];
  {
    int qx0 = (x0 >> 2) - 1, qy0 = (y0 >> 2) - 1;
    for (int i = tid; i < 21 * 4 * 10; i += 256) {
      int c = i / 40, rem = i % 40, yy = rem / 10, xx = rem % 10;
      int gy = min(max(qy0 + yy, 0), 127), gx = min(max(qx0 + xx, 0), 127);
      size_t idx = (size_t)((b * 21 + c) << 14) + (gy << 7) + gx;
      ms[c][yy][xx] = g_msgp[idx] + g_msgp[688128 + idx] +
                      g_msgp[2 * 688128 + idx] + g_msgp[3 * 688128 + idx];
    }
    __syncthreads();
  }
  const int pxp = tx & 3;
  const int ix0 = (tx >> 2) + (pxp >= 2 ? 1 : 0);
  const float wx0 = (pxp == 0) ? 0.375f : (pxp == 1) ? 0.125f : (pxp == 2) ? 0.875f : 0.625f;
  const float wx1 = 1.f - wx0;
  const int pyp = ty & 3;
  const int iy0 = (ty >> 2) + (pyp >= 2 ? 1 : 0);
  const float wy0 = (pyp == 0) ? 0.375f : (pyp == 1) ? 0.125f : (pyp == 2) ? 0.875f : 0.625f;
  const float wy1 = 1.f - wy0;
  const int y = y0 + ty, xg = x0 + tx;
  const float* up = g_unary + ((size_t)b * 21 << 18) + (y << 9) + xg;
  float* op = out + ((size_t)b * 21 << 18) + (y << 9) + xg;
#pragma unroll
  for (int c = 0; c < 21; c++) {
    float v = uw * up[(size_t)c << 18];
    float a  = wx0 * ms[c][iy0][ix0]     + wx1 * ms[c][iy0][ix0 + 1];
    float bb = wx0 * ms[c][iy0 + 1][ix0] + wx1 * ms[c][iy0 + 1][ix0 + 1];
    op[(size_t)c << 18] = v + wy0 * a + wy1 * bb;
  }
}

extern "C" void kernel_launch(void* const* d_in, const int* in_sizes, int n_in,
                              void* d_out, int out_size) {
  const float* x    = (const float*)d_in[0];
  const float* w    = (const float*)d_in[1];
  const float* bias = (const float*)d_in[2];
  const float* uw   = (const float*)d_in[3];
  const float* pw   = (const float*)d_in[4];
  float* out = (float*)d_out;
  (void)in_sizes; (void)n_in; (void)out_size;

  dim3 b32x8(32, 8);
  k_poolrgb<<<384, 256>>>(x);
  k_kernels<<<dim3(4, 16, 2), b32x8>>>(pw);
  k_convsoft<<<dim3(16, 64, 2), b32x8>>>(x, w, bias, uw);
  for (int t = 0; t < 5; t++) {
    k_pac<<<dim3(2, 32, 16), dim3(16, 4)>>>();
    if (t < 4) k_softpool<<<dim3(16, 64, 2), b32x8>>>(uw);
    else       k_final<<<dim3(16, 64, 2), b32x8>>>(uw, out);
  }
}

// round 16
// speedup vs baseline: 1.2302x; 1.0946x over previous
#include <cuda_runtime.h>

// ---------------- problem constants ----------------
// B=2, C=21, H=W=512, pooled 128x128, K=11 (radius 5), 5 steps, pad=(0,0)

// ---------------- scratch (device globals; no mallocs allowed) ----------------
__device__ float g_unary[11010048];   // [2][21][512][512]
__device__ float g_qb[688128];        // [2][21][128][128]
__device__ float g_msgp[2752512];     // [4 tap-groups][2][21][128][128] partial messages
__device__ float g_kcomb[3964928];    // [2][128y][121j][128x]  (y-major, j inner-contiguous rows)
__device__ float g_rgbp[98304];       // [2][3][128][128]    (already /13)

// ---------------- 4x4 avg-pool of x, folded /13 ----------------
__global__ void k_poolrgb(const float* __restrict__ x) {
  int idx = blockIdx.x * 256 + threadIdx.x;  // over 2*3*128*128
  if (idx >= 98304) return;
  int xp = idx & 127, yp = (idx >> 7) & 127, c = idx >> 14;  // c = b*3+ch
  const float* p = x + ((size_t)c << 18) + ((yp * 4) << 9) + (xp * 4);
  float s = 0.f;
#pragma unroll
  for (int i = 0; i < 4; i++)
#pragma unroll
    for (int j = 0; j < 4; j++) s += p[(i << 9) + j];
  g_rgbp[idx] = s * (1.0f / 208.0f);  // /16 pool, /13 feature scale
}

// ---------------- combined pairwise kernel: w1*bilateral + w2*spatial ----------------
// writes g_kcomb[b][y][j][x]
__global__ void k_kernels(const float* __restrict__ pw) {
  __shared__ float rs[3][18][42];
  __shared__ float sA[121], sS[121];
  const int b  = blockIdx.z;
  const int x0 = blockIdx.x * 32, y0 = blockIdx.y * 8;
  const int tx = threadIdx.x, ty = threadIdx.y;
  const int tid = ty * 32 + tx;
  if (tid < 121) {
    int dy = tid / 11 - 5, dx = tid % 11 - 5;
    float d2 = (float)(dy * dy + dx * dx);
    sA[tid] = __expf(-d2 * (1.0f / 800.0f));  // pooled YX/80: (4d/80)^2/2
    sS[tid] = __expf(-d2 * (8.0f / 9.0f));    // pooled YX/3 : (4d/3)^2/2
  }
  for (int i = tid; i < 3 * 18 * 42; i += 256) {
    int c = i / 756, rem = i % 756, yy = rem / 42, xx = rem % 42;
    int gy = y0 + yy - 5, gx = x0 + xx - 5;
    float v = 0.f;
    if (gy >= 0 && gy < 128 && gx >= 0 && gx < 128)
      v = g_rgbp[((b * 3 + c) << 14) + (gy << 7) + gx];
    rs[c][yy][xx] = v;
  }
  __syncthreads();
  const float w1 = pw[0], w2 = pw[1];
  const float r0 = rs[0][ty + 5][tx + 5];
  const float r1 = rs[1][ty + 5][tx + 5];
  const float r2 = rs[2][ty + 5][tx + 5];
  const int y = y0 + ty, xg = x0 + tx;
  float* outp = g_kcomb + (((size_t)(b * 128 + y) * 121) << 7) + xg;
  for (int dy = 0; dy < 11; dy++) {
    for (int dx = 0; dx < 11; dx++) {
      int j = dy * 11 + dx;
      int ny = y + dy - 5, nx = xg + dx - 5;
      float val = 0.f;  // OOB entries multiply zero-padded Q patches -> store 0
      if (ny >= 0 && ny < 128 && nx >= 0 && nx < 128) {
        float a = rs[0][ty + dy][tx + dx] - r0;
        float bb = rs[1][ty + dy][tx + dx] - r1;
        float cc = rs[2][ty + dy][tx + dx] - r2;
        float d2 = a * a + bb * bb + cc * cc;
        val = fmaf(w1 * sA[j], __expf(-0.5f * d2), w2 * sS[j]);
      }
      outp[j << 7] = val;
    }
  }
}

// ---------------- fused: conv(3->21) -> write unary -> softmax -> 4x4 pool ----------------
// block 32x8, grid (16,64,2)
__global__ void k_convsoft(const float* __restrict__ x, const float* __restrict__ w,
                           const float* __restrict__ bias, const float* __restrict__ uwp) {
  __shared__ float xs[3][10][34];
  __shared__ float ws[567];
  __shared__ float bs[21];
  __shared__ float ps[8][8][21];
  const int b  = blockIdx.z;
  const int x0 = blockIdx.x * 32, y0 = blockIdx.y * 8;
  const int tx = threadIdx.x, ty = threadIdx.y;
  const int tid = ty * 32 + tx;
  const float uw = uwp[0];
  for (int i = tid; i < 567; i += 256) ws[i] = w[i];
  if (tid < 21) bs[tid] = bias[tid];
  for (int i = tid; i < 3 * 10 * 34; i += 256) {
    int c = i / 340, rem = i % 340, yy = rem / 34, xx = rem % 34;
    int gy = y0 + yy - 1, gx = x0 + xx - 1;
    float v = 0.f;
    if (gy >= 0 && gy < 512 && gx >= 0 && gx < 512)
      v = x[((size_t)(b * 3 + c) << 18) + (gy << 9) + gx];
    xs[c][yy][xx] = v;
  }
  __syncthreads();
  float r[27];
#pragma unroll
  for (int c = 0; c < 3; c++)
#pragma unroll
    for (int ky = 0; ky < 3; ky++)
#pragma unroll
      for (int kx = 0; kx < 3; kx++)
        r[c * 9 + ky * 3 + kx] = xs[c][ty + ky][tx + kx];
  float* outp = g_unary + ((size_t)b * 21 << 18) + ((y0 + ty) << 9) + (x0 + tx);
  float logit[21];
  float mx = -1e30f;
#pragma unroll
  for (int o = 0; o < 21; o++) {
    float acc = bs[o];
#pragma unroll
    for (int i = 0; i < 27; i++) acc = fmaf(r[i], ws[o * 27 + i], acc);
    outp[(size_t)o << 18] = acc;
    float v = uw * acc;
    logit[o] = v;
    mx = fmaxf(mx, v);
  }
  float s = 0.f;
#pragma unroll
  for (int c = 0; c < 21; c++) { float e = __expf(logit[c] - mx); logit[c] = e; s += e; }
  float inv = __frcp_rn(s);
#pragma unroll
  for (int c = 0; c < 21; c++) {
    float q = logit[c] * inv;
    q += __shfl_down_sync(0xffffffffu, q, 1);
    q += __shfl_down_sync(0xffffffffu, q, 2);
    logit[c] = q;
  }
  if ((tx & 3) == 0) {
#pragma unroll
    for (int c = 0; c < 21; c++) ps[ty][tx >> 2][c] = logit[c];
  }
  __syncthreads();
  for (int i = tid; i < 336; i += 256) {
    int c = i % 21, pxx = (i / 21) & 7, pyy = i / 168;
    float sum = ps[pyy * 4 + 0][pxx][c] + ps[pyy * 4 + 1][pxx][c] +
                ps[pyy * 4 + 2][pxx][c] + ps[pyy * 4 + 3][pxx][c];
    int yp = (y0 >> 2) + pyy, xp = (x0 >> 2) + pxx;
    g_qb[((b * 21 + c) << 14) + (yp << 7) + xp] = sum * 0.0625f;
  }
}

// ---------------- fused: (uw*unary + upsample(msg)) -> softmax -> 4x4 pool ----------------
// 2 px/thread (float2 unary loads, shared bilinear column). block 32x8 covers
// 64x8 px; grid (8,64,2).
__global__ void k_softpool(const float* __restrict__ uwp) {
  __shared__ float ms[21][4][18];
  __shared__ float ps[8][16][21];
  const int b  = blockIdx.z;
  const int x0 = blockIdx.x * 64, y0 = blockIdx.y * 8;
  const int tx = threadIdx.x, ty = threadIdx.y;
  const int tid = ty * 32 + tx;
  const float uw = uwp[0];
  {
    int qx0 = (x0 >> 2) - 1, qy0 = (y0 >> 2) - 1;
    for (int i = tid; i < 21 * 4 * 18; i += 256) {
      int c = i / 72, rem = i % 72, yy = rem / 18, xx = rem % 18;
      int gy = min(max(qy0 + yy, 0), 127), gx = min(max(qx0 + xx, 0), 127);
      size_t idx = (size_t)((b * 21 + c) << 14) + (gy << 7) + gx;
      ms[c][yy][xx] = g_msgp[idx] + g_msgp[688128 + idx] +
                      g_msgp[2 * 688128 + idx] + g_msgp[3 * 688128 + idx];
    }
    __syncthreads();
  }
  // pixel pair px0 = 2tx (pix 0 or 2), px1 = 2tx+1 (pix 1 or 3): shared ix0
  const int odd = tx & 1;
  const int ix0 = (tx >> 1) + odd;
  const float wx0a = odd ? 0.875f : 0.375f;
  const float wx0b = odd ? 0.625f : 0.125f;
  const float wx1a = 1.f - wx0a, wx1b = 1.f - wx0b;
  const int pyp = ty & 3;
  const int iy0 = (ty >> 2) + (pyp >= 2 ? 1 : 0);
  const float wy0 = (pyp == 0) ? 0.375f : (pyp == 1) ? 0.125f : (pyp == 2) ? 0.875f : 0.625f;
  const float wy1 = 1.f - wy0;
  const int y = y0 + ty, xg = x0 + tx * 2;
  const float* up = g_unary + ((size_t)b * 21 << 18) + (y << 9) + xg;
  float l0[21], l1[21];
  float mx0 = -1e30f, mx1 = -1e30f;
#pragma unroll
  for (int c = 0; c < 21; c++) {
    float2 u = *reinterpret_cast<const float2*>(up + ((size_t)c << 18));
    float m00 = ms[c][iy0][ix0], m01 = ms[c][iy0][ix0 + 1];
    float m10 = ms[c][iy0 + 1][ix0], m11 = ms[c][iy0 + 1][ix0 + 1];
    float a0 = wx0a * m00 + wx1a * m01;
    float b0 = wx0a * m10 + wx1a * m11;
    float v0 = uw * u.x + (wy0 * a0 + wy1 * b0);
    float a1 = wx0b * m00 + wx1b * m01;
    float b1 = wx0b * m10 + wx1b * m11;
    float v1 = uw * u.y + (wy0 * a1 + wy1 * b1);
    l0[c] = v0; mx0 = fmaxf(mx0, v0);
    l1[c] = v1; mx1 = fmaxf(mx1, v1);
  }
  float s0 = 0.f, s1 = 0.f;
#pragma unroll
  for (int c = 0; c < 21; c++) {
    float e0 = __expf(l0[c] - mx0); l0[c] = e0; s0 += e0;
    float e1 = __expf(l1[c] - mx1); l1[c] = e1; s1 += e1;
  }
  float inv0 = __frcp_rn(s0), inv1 = __frcp_rn(s1);
#pragma unroll
  for (int c = 0; c < 21; c++) {
    float q = l0[c] * inv0 + l1[c] * inv1;          // (q0+q1)
    q += __shfl_xor_sync(0xffffffffu, q, 1);        // + (q2+q3)
    l0[c] = q;
  }
  if (!odd) {
#pragma unroll
    for (int c = 0; c < 21; c++) ps[ty][tx >> 1][c] = l0[c];
  }
  __syncthreads();
  for (int i = tid; i < 672; i += 256) {
    int c = i % 21, pxx = (i / 21) & 15, pyy = i / 336;
    float sum = ps[pyy * 4 + 0][pxx][c] + ps[pyy * 4 + 1][pxx][c] +
                ps[pyy * 4 + 2][pxx][c] + ps[pyy * 4 + 3][pxx][c];
    int yp = (y0 >> 2) + pyy, xp = (x0 >> 2) + pxx;
    g_qb[((b * 21 + c) << 14) + (yp << 7) + xp] = sum * 0.0625f;
  }
}

// ---------------- pixel-adaptive 11x11 message at 128x128 ----------------
// R8 structure (best known: tap-split x4, channel-split x2, 64px blocks,
// 11 ch x 4 px per thread, kv half-split) with the R12-validated vectorized
// fill: smem origin x0-8 so all chunks are aligned float4, pow2 indexing.
// grid (2,32,16): z = b*8 + g*2 + cg; tap rows [3g,3g+3) (g=3: [9,11)).
__global__ __launch_bounds__(64, 8) void k_pac() {
  __shared__ float qs[11][6][80];     // origin gx = x0-8, gy = qy0
  const int bz = blockIdx.z;
  const int b  = bz >> 3;
  const int g  = (bz >> 1) & 3;
  const int cg = bz & 1;
  const int s  = g * 3;
  const int nrr = (g == 3) ? 2 : 3;
  const int c0 = cg * 11;             // cg=1 covers c 11..20 (10 real + pad)
  const int x0 = blockIdx.x * 64;
  const int y0 = blockIdx.y * 4;
  const int tx = threadIdx.x;         // 0..15
  const int ty = threadIdx.y;         // 0..3
  const int tid = ty * 16 + tx;
  const int qy0 = y0 - 5 + s;
  // zero-fill smem (flat float4, no index math)
  {
    float4 z4 = make_float4(0.f, 0.f, 0.f, 0.f);
    float4* qsf = reinterpret_cast<float4*>(&qs[0][0][0]);
    for (int i = tid; i < 1320; i += 64) qsf[i] = z4;
  }
  __syncthreads();
  // vectorized fill: 6 rows x 20 aligned float4 chunks (virtual 32/row).
  {
    const int cmax = cg ? 10 : 11;
    for (int i = tid; i < 192; i += 64) {
      int r = i >> 5, k = i & 31;
      int gy = qy0 + r, gx = x0 - 8 + (k << 2);
      if (k < 20 && gy >= 0 && gy < 128 && gx >= 0 && gx < 128) {
        const float* src = g_qb + ((b * 21 + c0) << 14) + (gy << 7) + gx;
        float* dst = &qs[0][r][k << 2];
        for (int c = 0; c < cmax; c++)
          *reinterpret_cast<float4*>(dst + c * 480) =
              *reinterpret_cast<const float4*>(src + ((size_t)c << 14));
      }
    }
  }
  __syncthreads();
  const int y  = y0 + ty;
  const int xb = tx * 4;
  float acc[11][4];
#pragma unroll
  for (int c = 0; c < 11; c++)
#pragma unroll
    for (int o = 0; o < 4; o++) acc[c][o] = 0.f;
  for (int rr = s; rr < s + nrr; rr++) {
    const float4* kb = reinterpret_cast<const float4*>(
        g_kcomb + (((size_t)(b * 128 + y) * 121 + rr * 11) << 7) + x0 + xb);
    const int r = ty + rr - s;   // smem row index
    // ---- half A: dx 0..5; q rel floats [3..12] -> slots tx..tx+3 ----
    {
      float4 kv[6];
#pragma unroll
      for (int dx = 0; dx < 6; dx++) kv[dx] = __ldg(kb + (dx << 5));
#pragma unroll
      for (int c = 0; c < 11; c++) {
        const float4* qp = reinterpret_cast<const float4*>(&qs[c][r][0]) + tx;
        float4 q0 = qp[0], q1 = qp[1], q2 = qp[2], q3 = qp[3];
        float qf[16] = {q0.x, q0.y, q0.z, q0.w, q1.x, q1.y, q1.z, q1.w,
                        q2.x, q2.y, q2.z, q2.w, q3.x, q3.y, q3.z, q3.w};
#pragma unroll
        for (int dx = 0; dx < 6; dx++) {
          acc[c][0] = fmaf(kv[dx].x, qf[dx + 3], acc[c][0]);
          acc[c][1] = fmaf(kv[dx].y, qf[dx + 4], acc[c][1]);
          acc[c][2] = fmaf(kv[dx].z, qf[dx + 5], acc[c][2]);
          acc[c][3] = fmaf(kv[dx].w, qf[dx + 6], acc[c][3]);
        }
      }
    }
    // ---- half B: dx 6..10; q rel floats [9..16] -> slots tx+2..tx+4 ----
    {
      float4 kv[5];
#pragma unroll
      for (int d = 0; d < 5; d++) kv[d] = __ldg(kb + ((d + 6) << 5));
#pragma unroll
      for (int c = 0; c < 11; c++) {
        const float4* qp = reinterpret_cast<const float4*>(&qs[c][r][0]) + tx;
        float4 q2 = qp[2], q3 = qp[3], q4 = qp[4];
        float qf[12] = {q2.x, q2.y, q2.z, q2.w, q3.x, q3.y, q3.z, q3.w,
                        q4.x, q4.y, q4.z, q4.w};  // qf[i] = rel float 8+i
#pragma unroll
        for (int d = 0; d < 5; d++) {
          acc[c][0] = fmaf(kv[d].x, qf[d + 1], acc[c][0]);
          acc[c][1] = fmaf(kv[d].y, qf[d + 2], acc[c][1]);
          acc[c][2] = fmaf(kv[d].z, qf[d + 3], acc[c][2]);
          acc[c][3] = fmaf(kv[d].w, qf[d + 4], acc[c][3]);
        }
      }
    }
  }
  float* mp = g_msgp + (size_t)g * 688128 + ((size_t)(b * 21 + c0) << 14) + (y << 7) + x0 + xb;
#pragma unroll
  for (int c = 0; c < 11; c++) {
    if (c0 + c < 21) {
      float4 v = make_float4(acc[c][0], acc[c][1], acc[c][2], acc[c][3]);
      *reinterpret_cast<float4*>(mp + ((size_t)c << 14)) = v;
    }
  }
}

// ---------------- last step: logQ = uw*unary + upsample(msg) -> d_out ----------------
// 2 px/thread (float2). block 32x8 covers 64x8 px; grid (8,64,2).
__global__ void k_final(const float* __restrict__ uwp, float* __restrict__ out) {
  __shared__ float ms[21][4][18];
  const int b  = blockIdx.z;
  const int x0 = blockIdx.x * 64, y0 = blockIdx.y * 8;
  const int tx = threadIdx.x, ty = threadIdx.y;
  const int tid = ty * 32 + tx;
  const float uw = uwp[0];
  {
    int qx0 = (x0 >> 2) - 1, qy0 = (y0 >> 2) - 1;
    for (int i = tid; i < 21 * 4 * 18; i += 256) {
      int c = i / 72, rem = i % 72, yy = rem / 18, xx = rem % 18;
      int gy = min(max(qy0 + yy, 0), 127), gx = min(max(qx0 + xx, 0), 127);
      size_t idx = (size_t)((b * 21 + c) << 14) + (gy << 7) + gx;
      ms[c][yy][xx] = g_msgp[idx] + g_msgp[688128 + idx] +
                      g_msgp[2 * 688128 + idx] + g_msgp[3 * 688128 + idx];
    }
    __syncthreads();
  }
  const int odd = tx & 1;
  const int ix0 = (tx >> 1) + odd;
  const float wx0a = odd ? 0.875f : 0.375f;
  const float wx0b = odd ? 0.625f : 0.125f;
  const float wx1a = 1.f - wx0a, wx1b = 1.f - wx0b;
  const int pyp = ty & 3;
  const int iy0 = (ty >> 2) + (pyp >= 2 ? 1 : 0);
  const float wy0 = (pyp == 0) ? 0.375f : (pyp == 1) ? 0.125f : (pyp == 2) ? 0.875f : 0.625f;
  const float wy1 = 1.f - wy0;
  const int y = y0 + ty, xg = x0 + tx * 2;
  const float* up = g_unary + ((size_t)b * 21 << 18) + (y << 9) + xg;
  float* op = out + ((size_t)b * 21 << 18) + (y << 9) + xg;
#pragma unroll
  for (int c = 0; c < 21; c++) {
    float2 u = *reinterpret_cast<const float2*>(up + ((size_t)c << 18));
    float m00 = ms[c][iy0][ix0], m01 = ms[c][iy0][ix0 + 1];
    float m10 = ms[c][iy0 + 1][ix0], m11 = ms[c][iy0 + 1][ix0 + 1];
    float a0 = wx0a * m00 + wx1a * m01;
    float b0 = wx0a * m10 + wx1a * m11;
    float a1 = wx0b * m00 + wx1b * m01;
    float b1 = wx0b * m10 + wx1b * m11;
    float2 o;
    o.x = uw * u.x + (wy0 * a0 + wy1 * b0);
    o.y = uw * u.y + (wy0 * a1 + wy1 * b1);
    *reinterpret_cast<float2*>(op + ((size_t)c << 18)) = o;
  }
}

extern "C" void kernel_launch(void* const* d_in, const int* in_sizes, int n_in,
                              void* d_out, int out_size) {
  const float* x    = (const float*)d_in[0];
  const float* w    = (const float*)d_in[1];
  const float* bias = (const float*)d_in[2];
  const float* uw   = (const float*)d_in[3];
  const float* pw   = (const float*)d_in[4];
  float* out = (float*)d_out;
  (void)in_sizes; (void)n_in; (void)out_size;

  dim3 b32x8(32, 8);
  k_poolrgb<<<384, 256>>>(x);
  k_kernels<<<dim3(4, 16, 2), b32x8>>>(pw);
  k_convsoft<<<dim3(16, 64, 2), b32x8>>>(x, w, bias, uw);
  for (int t = 0; t < 5; t++) {
    k_pac<<<dim3(2, 32, 16), dim3(16, 4)>>>();
    if (t < 4) k_softpool<<<dim3(8, 64, 2), b32x8>>>(uw);
    else       k_final<<<dim3(8, 64, 2), b32x8>>>(uw, out);
  }
}